// round 4
// baseline (speedup 1.0000x reference)
#include <cuda_runtime.h>
#include <cuda_bf16.h>

#define UNITS 512
#define VOCAB 32000
#define BATCH 128
#define SEQ   64
#define ROWS  (BATCH * SEQ)   // 8192

typedef unsigned long long ull;

// ---------------- scratch (no allocations allowed) ----------------
__device__ float g_partial[4 * ROWS];        // attention col-block partial scores
__device__ float g_context[BATCH * UNITS];   // attention context
__device__ float g_y[BATCH * UNITS];         // dense output

// ---------------- packed f32x2 helpers (sm_100+) ----------------
__device__ __forceinline__ ull fma2(ull a, ull b, ull c) {
    ull d;
    asm("fma.rn.f32x2 %0, %1, %2, %3;" : "=l"(d) : "l"(a), "l"(b), "l"(c));
    return d;
}
__device__ __forceinline__ ull pack2(float x) {
    ull r;
    asm("mov.b64 %0, {%1, %1};" : "=l"(r) : "f"(x));
    return r;
}
__device__ __forceinline__ void unpack2(ull v, float& lo, float& hi) {
    asm("mov.b64 {%0, %1}, %2;" : "=f"(lo), "=f"(hi) : "l"(v));
}

// =====================================================================
// Kernel 1: attention GEMM  C = A(8192x512) @ W0(512x512)
//   fused epilogue: partial_score[row] += sum_col tanh(C+b0+b1)*vW[col]
//   tile 128x128, BK=16, 256 threads, 8x8 microtile, f32x2 packed FMA
// =====================================================================
__global__ __launch_bounds__(256) void attn_gemm_kernel(
    const float* __restrict__ A,
    const float* __restrict__ W0,
    const float* __restrict__ b0,
    const float* __restrict__ b1,
    const float* __restrict__ vW)
{
    __shared__ float As[16][128];
    __shared__ float Bs[16][128];
    __shared__ float red[128][17];

    const int bx = blockIdx.x;            // col block 0..3
    const int by = blockIdx.y;            // row block 0..63
    const int tid = threadIdx.x;
    const int tx = tid & 15, ty = tid >> 4;
    const int rowBase = by * 128, colBase = bx * 128;

    ull acc2[4][8];                       // row-pairs x 8 cols
    #pragma unroll
    for (int i = 0; i < 4; i++)
        #pragma unroll
        for (int j = 0; j < 8; j++) acc2[i][j] = 0ull;

    for (int k0 = 0; k0 < UNITS; k0 += 16) {
        #pragma unroll
        for (int it = 0; it < 2; it++) {
            int idx = tid + it * 256;
            int m   = idx >> 2;
            int k4  = (idx & 3) * 4;
            float4 v = *(const float4*)&A[(size_t)(rowBase + m) * UNITS + k0 + k4];
            As[k4 + 0][m] = v.x; As[k4 + 1][m] = v.y;
            As[k4 + 2][m] = v.z; As[k4 + 3][m] = v.w;
        }
        #pragma unroll
        for (int it = 0; it < 2; it++) {
            int idx = tid + it * 256;
            int kk  = idx >> 5;
            int n4  = (idx & 31) * 4;
            *(float4*)&Bs[kk][n4] =
                *(const float4*)&W0[(size_t)(k0 + kk) * UNITS + colBase + n4];
        }
        __syncthreads();

        #pragma unroll
        for (int kk = 0; kk < 16; kk++) {
            ull a2[4];
            a2[0] = *(const ull*)&As[kk][ty * 4];
            a2[1] = *(const ull*)&As[kk][ty * 4 + 2];
            a2[2] = *(const ull*)&As[kk][ty * 4 + 64];
            a2[3] = *(const ull*)&As[kk][ty * 4 + 66];
            float bn[8];
            *(float4*)&bn[0] = *(const float4*)&Bs[kk][tx * 4];
            *(float4*)&bn[4] = *(const float4*)&Bs[kk][tx * 4 + 64];
            #pragma unroll
            for (int j = 0; j < 8; j++) {
                ull b2 = pack2(bn[j]);
                #pragma unroll
                for (int ih = 0; ih < 4; ih++)
                    acc2[ih][j] = fma2(a2[ih], b2, acc2[ih][j]);
            }
        }
        __syncthreads();
    }

    // unpack -> acc[8][8] in original (i,j) order
    float acc[8][8];
    #pragma unroll
    for (int ih = 0; ih < 4; ih++)
        #pragma unroll
        for (int j = 0; j < 8; j++)
            unpack2(acc2[ih][j], acc[2 * ih][j], acc[2 * ih + 1][j]);

    // epilogue: tanh(acc + b0 + b1) * vW, reduce over columns
    float part[8];
    #pragma unroll
    for (int i = 0; i < 8; i++) part[i] = 0.f;
    #pragma unroll
    for (int j = 0; j < 8; j++) {
        int nl  = (j < 4) ? (tx * 4 + j) : (tx * 4 + 64 + (j - 4));
        int col = colBase + nl;
        float bias = b0[col] + b1[col];
        float v    = vW[col];
        #pragma unroll
        for (int i = 0; i < 8; i++)
            part[i] += tanhf(acc[i][j] + bias) * v;
    }
    #pragma unroll
    for (int i = 0; i < 8; i++) {
        int ml = (i < 4) ? (ty * 4 + i) : (ty * 4 + 64 + (i - 4));
        red[ml][tx] = part[i];
    }
    __syncthreads();
    if (tid < 128) {
        float s = 0.f;
        #pragma unroll
        for (int t = 0; t < 16; t++) s += red[tid][t];
        g_partial[bx * ROWS + rowBase + tid] = s;
    }
}

// =====================================================================
// Kernel 2: per-batch softmax over SEQ + context = sum_s alpha*A[b,s,:]
// =====================================================================
__global__ __launch_bounds__(256) void softmax_ctx_kernel(
    const float* __restrict__ A,
    float* __restrict__ alpha_out)
{
    __shared__ float al[SEQ];
    __shared__ float mx, ssum;
    const int b = blockIdx.x;
    const int tid = threadIdx.x;

    if (tid < SEQ) {
        float s = 0.f;
        #pragma unroll
        for (int cb = 0; cb < 4; cb++) s += g_partial[cb * ROWS + b * SEQ + tid];
        al[tid] = s;
    }
    __syncthreads();
    if (tid == 0) {
        float m = -1e30f;
        for (int i = 0; i < SEQ; i++) m = fmaxf(m, al[i]);
        mx = m;
    }
    __syncthreads();
    if (tid < SEQ) al[tid] = expf(al[tid] - mx);
    __syncthreads();
    if (tid == 0) {
        float s = 0.f;
        for (int i = 0; i < SEQ; i++) s += al[i];
        ssum = s;
    }
    __syncthreads();
    if (tid < SEQ) {
        al[tid] = al[tid] / ssum;
        alpha_out[b * SEQ + tid] = al[tid];
    }
    __syncthreads();

    for (int u = tid; u < UNITS; u += 256) {
        float c = 0.f;
        #pragma unroll 8
        for (int s = 0; s < SEQ; s++)
            c += al[s] * A[((size_t)(b * SEQ + s)) * UNITS + u];
        g_context[b * UNITS + u] = c;
    }
}

// =====================================================================
// Kernel 3: GRU.  xc = [emb[inputs[b]], context[b]] (128x1024)
// =====================================================================
__global__ __launch_bounds__(256) void gru_kernel(
    const int*   __restrict__ inputs,
    const float* __restrict__ emb,
    const float* __restrict__ gru_k,
    const float* __restrict__ gru_b,
    float* __restrict__ state_out)
{
    __shared__ float Xs[32][33];        // [k][b]
    __shared__ float Gs[3][32][64];
    const int jb = blockIdx.x * 64;
    const int bb = blockIdx.y * 32;
    const int tid = threadIdx.x;
    const int tx = tid & 15, ty = tid >> 4;

    float acc[3][2][4];
    #pragma unroll
    for (int g = 0; g < 3; g++)
        #pragma unroll
        for (int bi = 0; bi < 2; bi++)
            #pragma unroll
            for (int j = 0; j < 4; j++) acc[g][bi][j] = 0.f;

    for (int k0 = 0; k0 < 2 * UNITS; k0 += 32) {
        {
            int bl = tid >> 3;
            int k4 = (tid & 7) * 4;
            int k  = k0 + k4;
            float4 v;
            if (k < UNITS) {
                int row = inputs[bb + bl];
                v = *(const float4*)&emb[(size_t)row * UNITS + k];
            } else {
                v = *(const float4*)&g_context[(size_t)(bb + bl) * UNITS + (k - UNITS)];
            }
            Xs[k4 + 0][bl] = v.x; Xs[k4 + 1][bl] = v.y;
            Xs[k4 + 2][bl] = v.z; Xs[k4 + 3][bl] = v.w;
        }
        #pragma unroll
        for (int g = 0; g < 3; g++) {
            #pragma unroll
            for (int it = 0; it < 2; it++) {
                int idx = tid + it * 256;
                int kk  = idx >> 4;
                int j4  = (idx & 15) * 4;
                *(float4*)&Gs[g][kk][j4] =
                    *(const float4*)&gru_k[(size_t)(k0 + kk) * (3 * UNITS) + g * UNITS + jb + j4];
            }
        }
        __syncthreads();

        #pragma unroll 8
        for (int kk = 0; kk < 32; kk++) {
            float xb0 = Xs[kk][ty * 2];
            float xb1 = Xs[kk][ty * 2 + 1];
            #pragma unroll
            for (int g = 0; g < 3; g++) {
                float4 gv = *(float4*)&Gs[g][kk][tx * 4];
                float gj[4] = {gv.x, gv.y, gv.z, gv.w};
                #pragma unroll
                for (int j = 0; j < 4; j++) {
                    acc[g][0][j] += xb0 * gj[j];
                    acc[g][1][j] += xb1 * gj[j];
                }
            }
        }
        __syncthreads();
    }

    #pragma unroll
    for (int j = 0; j < 4; j++) {
        int jg = jb + tx * 4 + j;
        float bz = gru_b[jg];
        float br = gru_b[UNITS + jg];
        float bh = gru_b[2 * UNITS + jg];
        float rz = gru_b[3 * UNITS + jg];
        float rr = gru_b[4 * UNITS + jg];
        float rh = gru_b[5 * UNITS + jg];
        #pragma unroll
        for (int bi = 0; bi < 2; bi++) {
            int b = bb + ty * 2 + bi;
            float z  = 1.f / (1.f + expf(-(acc[0][bi][j] + bz + rz)));
            float r  = 1.f / (1.f + expf(-(acc[1][bi][j] + br + rr)));
            float hh = tanhf(acc[2][bi][j] + bh + r * rh);
            state_out[(size_t)b * UNITS + jg] = (1.f - z) * hh;
        }
    }
}

// =====================================================================
// Kernel 4: y = relu(state @ dW + db), tile 32x64, BK=32, grid 32 blocks
// =====================================================================
__global__ __launch_bounds__(256) void dense_kernel(
    const float* __restrict__ state,
    const float* __restrict__ dW,
    const float* __restrict__ db)
{
    __shared__ float As[32][36];
    __shared__ float Bs[32][64];
    const int colBase = blockIdx.x * 64;
    const int rowBase = blockIdx.y * 32;
    const int tid = threadIdx.x;
    const int tx = tid & 15, ty = tid >> 4;

    float acc[2][4];
    #pragma unroll
    for (int i = 0; i < 2; i++)
        #pragma unroll
        for (int j = 0; j < 4; j++) acc[i][j] = 0.f;

    for (int k0 = 0; k0 < UNITS; k0 += 32) {
        {
            int m  = tid >> 3;              // 0..31
            int k4 = (tid & 7) * 4;         // 0..28
            float4 v = *(const float4*)&state[(size_t)(rowBase + m) * UNITS + k0 + k4];
            As[k4 + 0][m] = v.x; As[k4 + 1][m] = v.y;
            As[k4 + 2][m] = v.z; As[k4 + 3][m] = v.w;
        }
        #pragma unroll
        for (int it = 0; it < 2; it++) {
            int idx = tid + it * 256;
            int kk  = idx >> 4;
            int n4  = (idx & 15) * 4;
            *(float4*)&Bs[kk][n4] =
                *(const float4*)&dW[(size_t)(k0 + kk) * UNITS + colBase + n4];
        }
        __syncthreads();
        #pragma unroll
        for (int kk = 0; kk < 32; kk++) {
            float a0 = As[kk][ty * 2];
            float a1 = As[kk][ty * 2 + 1];
            float4 b4 = *(const float4*)&Bs[kk][tx * 4];
            acc[0][0] += a0 * b4.x; acc[0][1] += a0 * b4.y;
            acc[0][2] += a0 * b4.z; acc[0][3] += a0 * b4.w;
            acc[1][0] += a1 * b4.x; acc[1][1] += a1 * b4.y;
            acc[1][2] += a1 * b4.z; acc[1][3] += a1 * b4.w;
        }
        __syncthreads();
    }

    #pragma unroll
    for (int i = 0; i < 2; i++) {
        int m = rowBase + ty * 2 + i;
        float4 o;
        o.x = fmaxf(acc[i][0] + db[colBase + tx * 4 + 0], 0.f);
        o.y = fmaxf(acc[i][1] + db[colBase + tx * 4 + 1], 0.f);
        o.z = fmaxf(acc[i][2] + db[colBase + tx * 4 + 2], 0.f);
        o.w = fmaxf(acc[i][3] + db[colBase + tx * 4 + 3], 0.f);
        *(float4*)&g_y[(size_t)m * UNITS + colBase + tx * 4] = o;
    }
}

// =====================================================================
// Kernel 5: logits = y(128x512) @ oW(512x32000) + ob
//   tile 128x128, BK=16, 256 threads, 8x8 micro, f32x2 packed FMA
// =====================================================================
__global__ __launch_bounds__(256) void logits_kernel(
    const float* __restrict__ oW,
    const float* __restrict__ ob,
    float* __restrict__ out)
{
    __shared__ float As[16][128];
    __shared__ float Bs[16][128];
    const int colBase = blockIdx.x * 128;
    const int tid = threadIdx.x;
    const int tx = tid & 15, ty = tid >> 4;

    ull acc2[4][8];
    #pragma unroll
    for (int i = 0; i < 4; i++)
        #pragma unroll
        for (int j = 0; j < 8; j++) acc2[i][j] = 0ull;

    for (int k0 = 0; k0 < UNITS; k0 += 16) {
        #pragma unroll
        for (int it = 0; it < 2; it++) {
            int idx = tid + it * 256;
            int m   = idx >> 2;
            int k4  = (idx & 3) * 4;
            float4 v = *(const float4*)&g_y[(size_t)m * UNITS + k0 + k4];
            As[k4 + 0][m] = v.x; As[k4 + 1][m] = v.y;
            As[k4 + 2][m] = v.z; As[k4 + 3][m] = v.w;
        }
        #pragma unroll
        for (int it = 0; it < 2; it++) {
            int idx = tid + it * 256;
            int kk  = idx >> 5;
            int n4  = (idx & 31) * 4;
            *(float4*)&Bs[kk][n4] =
                *(const float4*)&oW[(size_t)(k0 + kk) * VOCAB + colBase + n4];
        }
        __syncthreads();
        #pragma unroll
        for (int kk = 0; kk < 16; kk++) {
            ull a2[4];
            a2[0] = *(const ull*)&As[kk][ty * 4];
            a2[1] = *(const ull*)&As[kk][ty * 4 + 2];
            a2[2] = *(const ull*)&As[kk][ty * 4 + 64];
            a2[3] = *(const ull*)&As[kk][ty * 4 + 66];
            float bn[8];
            *(float4*)&bn[0] = *(const float4*)&Bs[kk][tx * 4];
            *(float4*)&bn[4] = *(const float4*)&Bs[kk][tx * 4 + 64];
            #pragma unroll
            for (int j = 0; j < 8; j++) {
                ull b2 = pack2(bn[j]);
                #pragma unroll
                for (int ih = 0; ih < 4; ih++)
                    acc2[ih][j] = fma2(a2[ih], b2, acc2[ih][j]);
            }
        }
        __syncthreads();
    }

    float acc[8][8];
    #pragma unroll
    for (int ih = 0; ih < 4; ih++)
        #pragma unroll
        for (int j = 0; j < 8; j++)
            unpack2(acc2[ih][j], acc[2 * ih][j], acc[2 * ih + 1][j]);

    #pragma unroll
    for (int i = 0; i < 8; i++) {
        int m = (i < 4) ? (ty * 4 + i) : (ty * 4 + 64 + (i - 4));
        #pragma unroll
        for (int jh = 0; jh < 2; jh++) {
            int nl = tx * 4 + jh * 64;
            float4 o;
            o.x = acc[i][jh * 4 + 0] + ob[colBase + nl + 0];
            o.y = acc[i][jh * 4 + 1] + ob[colBase + nl + 1];
            o.z = acc[i][jh * 4 + 2] + ob[colBase + nl + 2];
            o.w = acc[i][jh * 4 + 3] + ob[colBase + nl + 3];
            *(float4*)&out[(size_t)m * VOCAB + colBase + nl] = o;
        }
    }
}

// =====================================================================
extern "C" void kernel_launch(void* const* d_in, const int* in_sizes, int n_in,
                              void* d_out, int out_size)
{
    const int*   inputs = (const int*)  d_in[0];
    const float* A      = (const float*)d_in[1];   // attention_inputs
    const float* W0     = (const float*)d_in[2];
    const float* b0     = (const float*)d_in[3];
    // d_in[4] = W1   (multiplied by structural zero hidden0 -> unused)
    const float* b1     = (const float*)d_in[5];
    const float* vW     = (const float*)d_in[6];
    // d_in[7] = vb   (uniform shift before softmax -> cancels exactly)
    const float* emb    = (const float*)d_in[8];
    const float* gru_k  = (const float*)d_in[9];
    // d_in[10] = gru_rk (multiplied by structural zero h -> unused)
    const float* gru_b  = (const float*)d_in[11];
    const float* dW     = (const float*)d_in[12];
    const float* db     = (const float*)d_in[13];
    const float* oW     = (const float*)d_in[14];
    const float* ob     = (const float*)d_in[15];

    float* out    = (float*)d_out;
    float* logits = out;                                   // 128*32000
    float* state  = out + (size_t)BATCH * VOCAB;           // 128*512
    float* alpha  = state + (size_t)BATCH * UNITS;         // 128*64

    attn_gemm_kernel<<<dim3(4, 64), 256>>>(A, W0, b0, b1, vW);
    softmax_ctx_kernel<<<BATCH, 256>>>(A, alpha);
    gru_kernel<<<dim3(8, 4), 256>>>(inputs, emb, gru_k, gru_b, state);
    dense_kernel<<<dim3(8, 4), 256>>>(state, dW, db);
    logits_kernel<<<dim3(VOCAB / 128, 1), 256>>>(oW, ob, logits);
}

// round 7
// speedup vs baseline: 1.5357x; 1.5357x over previous
#include <cuda_runtime.h>
#include <cuda_bf16.h>

#define UNITS 512
#define VOCAB 32000
#define BATCH 128
#define SEQ   64
#define ROWS  (BATCH * SEQ)   // 8192

// ---------------- scratch (no allocations allowed) ----------------
__device__ float g_partial[4 * ROWS];        // attention col-block partial scores
__device__ float g_context[BATCH * UNITS];   // attention context
__device__ float g_y[BATCH * UNITS];         // dense output

// ---------------- tf32 mma helpers ----------------
__device__ __forceinline__ unsigned f2tf32(float x) {
    unsigned r;
    asm("cvt.rna.tf32.f32 %0, %1;" : "=r"(r) : "f"(x));
    return r;
}
__device__ __forceinline__ void mma_tf32(
    float& d0, float& d1, float& d2, float& d3,
    unsigned a0, unsigned a1, unsigned a2, unsigned a3,
    unsigned b0, unsigned b1)
{
    asm("mma.sync.aligned.m16n8k8.row.col.f32.tf32.tf32.f32 "
        "{%0,%1,%2,%3}, {%4,%5,%6,%7}, {%8,%9}, {%0,%1,%2,%3};"
        : "+f"(d0), "+f"(d1), "+f"(d2), "+f"(d3)
        : "r"(a0), "r"(a1), "r"(a2), "r"(a3), "r"(b0), "r"(b1));
}

// =====================================================================
// Kernel 1: attention GEMM  C = A(8192x512) @ W0(512x512)  [tf32 mma]
//   block tile 128x128, BK=32, 8 warps (warp tile 32x64)
//   fused epilogue: partial_score[row] = sum_col tanh(C+b0+b1)*vW[col]
// =====================================================================
__global__ __launch_bounds__(256) void attn_gemm_kernel(
    const float* __restrict__ A,
    const float* __restrict__ W0,
    const float* __restrict__ b0,
    const float* __restrict__ b1,
    const float* __restrict__ vW)
{
    __shared__ unsigned As[128][36];   // [m][k], pad 36: frag banks 4g+c distinct
    __shared__ unsigned Bs[32][132];   // [k][n], pad 132: frag banks 4c+g distinct
    __shared__ float bias_s[128];
    __shared__ float v_s[128];
    __shared__ float red[128][2];

    const int bx = blockIdx.x;            // col block 0..3
    const int by = blockIdx.y;            // row block 0..63
    const int tid  = threadIdx.x;
    const int lane = tid & 31;
    const int warp = tid >> 5;
    const int wm = warp & 3;              // warp row 0..3 (32 rows each)
    const int wn = warp >> 2;             // warp col 0..1 (64 cols each)
    const int g  = lane >> 2;             // 0..7
    const int c  = lane & 3;              // 0..3
    const int mb = wm * 32;
    const int nb = wn * 64;
    const int rowBase = by * 128, colBase = bx * 128;

    if (tid < 128) {
        bias_s[tid] = b0[colBase + tid] + b1[colBase + tid];
        v_s[tid]    = vW[colBase + tid];
    }

    float acc[2][8][4];
    #pragma unroll
    for (int i = 0; i < 2; i++)
        #pragma unroll
        for (int j = 0; j < 8; j++)
            #pragma unroll
            for (int t = 0; t < 4; t++) acc[i][j][t] = 0.f;

    for (int k0 = 0; k0 < UNITS; k0 += 32) {
        #pragma unroll
        for (int it = 0; it < 4; it++) {
            int q  = tid + it * 256;        // 1024 float4 slots
            int m  = q >> 3;
            int k4 = (q & 7) * 4;
            float4 v = *(const float4*)&A[(size_t)(rowBase + m) * UNITS + k0 + k4];
            uint4 u;
            u.x = f2tf32(v.x); u.y = f2tf32(v.y);
            u.z = f2tf32(v.z); u.w = f2tf32(v.w);
            *(uint4*)&As[m][k4] = u;
        }
        #pragma unroll
        for (int it = 0; it < 4; it++) {
            int q  = tid + it * 256;
            int kk = q >> 5;
            int n4 = (q & 31) * 4;
            float4 v = *(const float4*)&W0[(size_t)(k0 + kk) * UNITS + colBase + n4];
            uint4 u;
            u.x = f2tf32(v.x); u.y = f2tf32(v.y);
            u.z = f2tf32(v.z); u.w = f2tf32(v.w);
            *(uint4*)&Bs[kk][n4] = u;
        }
        __syncthreads();

        #pragma unroll
        for (int kk = 0; kk < 4; kk++) {
            int kc = kk * 8 + c;
            unsigned a[2][4];
            #pragma unroll
            for (int i = 0; i < 2; i++) {
                int r = mb + i * 16 + g;
                a[i][0] = As[r][kc];
                a[i][1] = As[r + 8][kc];
                a[i][2] = As[r][kc + 4];
                a[i][3] = As[r + 8][kc + 4];
            }
            #pragma unroll
            for (int j = 0; j < 8; j++) {
                int n = nb + j * 8 + g;
                unsigned bb0 = Bs[kc][n];
                unsigned bb1 = Bs[kc + 4][n];
                #pragma unroll
                for (int i = 0; i < 2; i++)
                    mma_tf32(acc[i][j][0], acc[i][j][1], acc[i][j][2], acc[i][j][3],
                             a[i][0], a[i][1], a[i][2], a[i][3], bb0, bb1);
            }
        }
        __syncthreads();
    }

    // epilogue: part[rowlocal] = sum_col tanh(acc + bias)*v
    // thread rows: mb + i*16 + g (c0,c1) and +8 (c2,c3); cols: nb + j*8 + 2c (+1)
    float part[4];
    #pragma unroll
    for (int t = 0; t < 4; t++) part[t] = 0.f;
    #pragma unroll
    for (int i = 0; i < 2; i++) {
        #pragma unroll
        for (int j = 0; j < 8; j++) {
            int n0 = nb + j * 8 + 2 * c;
            float bv0 = bias_s[n0],     vv0 = v_s[n0];
            float bv1 = bias_s[n0 + 1], vv1 = v_s[n0 + 1];
            part[2 * i]     += tanhf(acc[i][j][0] + bv0) * vv0
                             + tanhf(acc[i][j][1] + bv1) * vv1;
            part[2 * i + 1] += tanhf(acc[i][j][2] + bv0) * vv0
                             + tanhf(acc[i][j][3] + bv1) * vv1;
        }
    }
    // reduce over the 4 lanes sharing the same g (c = 0..3)
    #pragma unroll
    for (int t = 0; t < 4; t++) {
        part[t] += __shfl_xor_sync(0xffffffffu, part[t], 1);
        part[t] += __shfl_xor_sync(0xffffffffu, part[t], 2);
    }
    if (c == 0) {
        red[mb + g][wn]      = part[0];
        red[mb + 8 + g][wn]  = part[1];
        red[mb + 16 + g][wn] = part[2];
        red[mb + 24 + g][wn] = part[3];
    }
    __syncthreads();
    if (tid < 128)
        g_partial[bx * ROWS + rowBase + tid] = red[tid][0] + red[tid][1];
}

// =====================================================================
// Kernel 2: per-batch softmax over SEQ + context = sum_s alpha*A[b,s,:]
// =====================================================================
__global__ __launch_bounds__(256) void softmax_ctx_kernel(
    const float* __restrict__ A,
    float* __restrict__ alpha_out)
{
    __shared__ float al[SEQ];
    __shared__ float mx, ssum;
    const int b = blockIdx.x;
    const int tid = threadIdx.x;

    if (tid < SEQ) {
        float s = 0.f;
        #pragma unroll
        for (int cb = 0; cb < 4; cb++) s += g_partial[cb * ROWS + b * SEQ + tid];
        al[tid] = s;
    }
    __syncthreads();
    if (tid == 0) {
        float m = -1e30f;
        for (int i = 0; i < SEQ; i++) m = fmaxf(m, al[i]);
        mx = m;
    }
    __syncthreads();
    if (tid < SEQ) al[tid] = expf(al[tid] - mx);
    __syncthreads();
    if (tid == 0) {
        float s = 0.f;
        for (int i = 0; i < SEQ; i++) s += al[i];
        ssum = s;
    }
    __syncthreads();
    if (tid < SEQ) {
        al[tid] = al[tid] / ssum;
        alpha_out[b * SEQ + tid] = al[tid];
    }
    __syncthreads();

    for (int u = tid; u < UNITS; u += 256) {
        float cacc = 0.f;
        #pragma unroll 8
        for (int s = 0; s < SEQ; s++)
            cacc += al[s] * A[((size_t)(b * SEQ + s)) * UNITS + u];
        g_context[b * UNITS + u] = cacc;
    }
}

// =====================================================================
// Kernel 3: GRU.  xc = [emb[inputs[b]], context[b]] (128x1024)
// =====================================================================
__global__ __launch_bounds__(256) void gru_kernel(
    const int*   __restrict__ inputs,
    const float* __restrict__ emb,
    const float* __restrict__ gru_k,
    const float* __restrict__ gru_b,
    float* __restrict__ state_out)
{
    __shared__ float Xs[32][33];        // [k][b]
    __shared__ float Gs[3][32][64];
    const int jb = blockIdx.x * 64;
    const int bb = blockIdx.y * 32;
    const int tid = threadIdx.x;
    const int tx = tid & 15, ty = tid >> 4;

    float acc[3][2][4];
    #pragma unroll
    for (int g = 0; g < 3; g++)
        #pragma unroll
        for (int bi = 0; bi < 2; bi++)
            #pragma unroll
            for (int j = 0; j < 4; j++) acc[g][bi][j] = 0.f;

    for (int k0 = 0; k0 < 2 * UNITS; k0 += 32) {
        {
            int bl = tid >> 3;
            int k4 = (tid & 7) * 4;
            int k  = k0 + k4;
            float4 v;
            if (k < UNITS) {
                int row = inputs[bb + bl];
                v = *(const float4*)&emb[(size_t)row * UNITS + k];
            } else {
                v = *(const float4*)&g_context[(size_t)(bb + bl) * UNITS + (k - UNITS)];
            }
            Xs[k4 + 0][bl] = v.x; Xs[k4 + 1][bl] = v.y;
            Xs[k4 + 2][bl] = v.z; Xs[k4 + 3][bl] = v.w;
        }
        #pragma unroll
        for (int g = 0; g < 3; g++) {
            #pragma unroll
            for (int it = 0; it < 2; it++) {
                int idx = tid + it * 256;
                int kk  = idx >> 4;
                int j4  = (idx & 15) * 4;
                *(float4*)&Gs[g][kk][j4] =
                    *(const float4*)&gru_k[(size_t)(k0 + kk) * (3 * UNITS) + g * UNITS + jb + j4];
            }
        }
        __syncthreads();

        #pragma unroll 8
        for (int kk = 0; kk < 32; kk++) {
            float xb0 = Xs[kk][ty * 2];
            float xb1 = Xs[kk][ty * 2 + 1];
            #pragma unroll
            for (int g = 0; g < 3; g++) {
                float4 gv = *(float4*)&Gs[g][kk][tx * 4];
                float gj[4] = {gv.x, gv.y, gv.z, gv.w};
                #pragma unroll
                for (int j = 0; j < 4; j++) {
                    acc[g][0][j] += xb0 * gj[j];
                    acc[g][1][j] += xb1 * gj[j];
                }
            }
        }
        __syncthreads();
    }

    #pragma unroll
    for (int j = 0; j < 4; j++) {
        int jg = jb + tx * 4 + j;
        float bz = gru_b[jg];
        float br = gru_b[UNITS + jg];
        float bh = gru_b[2 * UNITS + jg];
        float rz = gru_b[3 * UNITS + jg];
        float rr = gru_b[4 * UNITS + jg];
        float rh = gru_b[5 * UNITS + jg];
        #pragma unroll
        for (int bi = 0; bi < 2; bi++) {
            int b = bb + ty * 2 + bi;
            float z  = 1.f / (1.f + expf(-(acc[0][bi][j] + bz + rz)));
            float r  = 1.f / (1.f + expf(-(acc[1][bi][j] + br + rr)));
            float hh = tanhf(acc[2][bi][j] + bh + r * rh);
            state_out[(size_t)b * UNITS + jg] = (1.f - z) * hh;
        }
    }
}

// =====================================================================
// Kernel 4: y = relu(state @ dW + db), tile 32x64, BK=32, grid 32 blocks
// =====================================================================
__global__ __launch_bounds__(256) void dense_kernel(
    const float* __restrict__ state,
    const float* __restrict__ dW,
    const float* __restrict__ db)
{
    __shared__ float As[32][36];
    __shared__ float Bs[32][64];
    const int colBase = blockIdx.x * 64;
    const int rowBase = blockIdx.y * 32;
    const int tid = threadIdx.x;
    const int tx = tid & 15, ty = tid >> 4;

    float acc[2][4];
    #pragma unroll
    for (int i = 0; i < 2; i++)
        #pragma unroll
        for (int j = 0; j < 4; j++) acc[i][j] = 0.f;

    for (int k0 = 0; k0 < UNITS; k0 += 32) {
        {
            int m  = tid >> 3;              // 0..31
            int k4 = (tid & 7) * 4;         // 0..28
            float4 v = *(const float4*)&state[(size_t)(rowBase + m) * UNITS + k0 + k4];
            As[k4 + 0][m] = v.x; As[k4 + 1][m] = v.y;
            As[k4 + 2][m] = v.z; As[k4 + 3][m] = v.w;
        }
        #pragma unroll
        for (int it = 0; it < 2; it++) {
            int idx = tid + it * 256;
            int kk  = idx >> 4;
            int n4  = (idx & 15) * 4;
            *(float4*)&Bs[kk][n4] =
                *(const float4*)&dW[(size_t)(k0 + kk) * UNITS + colBase + n4];
        }
        __syncthreads();
        #pragma unroll
        for (int kk = 0; kk < 32; kk++) {
            float a0 = As[kk][ty * 2];
            float a1 = As[kk][ty * 2 + 1];
            float4 b4 = *(const float4*)&Bs[kk][tx * 4];
            acc[0][0] += a0 * b4.x; acc[0][1] += a0 * b4.y;
            acc[0][2] += a0 * b4.z; acc[0][3] += a0 * b4.w;
            acc[1][0] += a1 * b4.x; acc[1][1] += a1 * b4.y;
            acc[1][2] += a1 * b4.z; acc[1][3] += a1 * b4.w;
        }
        __syncthreads();
    }

    #pragma unroll
    for (int i = 0; i < 2; i++) {
        int m = rowBase + ty * 2 + i;
        float4 o;
        o.x = fmaxf(acc[i][0] + db[colBase + tx * 4 + 0], 0.f);
        o.y = fmaxf(acc[i][1] + db[colBase + tx * 4 + 1], 0.f);
        o.z = fmaxf(acc[i][2] + db[colBase + tx * 4 + 2], 0.f);
        o.w = fmaxf(acc[i][3] + db[colBase + tx * 4 + 3], 0.f);
        *(float4*)&g_y[(size_t)m * UNITS + colBase + tx * 4] = o;
    }
}

// =====================================================================
// Kernel 5: logits = y(128x512) @ oW(512x32000) + ob  [tf32 mma]
//   block tile 128x128, BK=32, 8 warps (warp tile 32x64)
// =====================================================================
__global__ __launch_bounds__(256) void logits_kernel(
    const float* __restrict__ oW,
    const float* __restrict__ ob,
    float* __restrict__ out)
{
    __shared__ unsigned As[128][36];
    __shared__ unsigned Bs[32][132];
    __shared__ float obs[128];

    const int colBase = blockIdx.x * 128;
    const int tid  = threadIdx.x;
    const int lane = tid & 31;
    const int warp = tid >> 5;
    const int wm = warp & 3;
    const int wn = warp >> 2;
    const int g  = lane >> 2;
    const int c  = lane & 3;
    const int mb = wm * 32;
    const int nb = wn * 64;

    if (tid < 128) obs[tid] = ob[colBase + tid];

    float acc[2][8][4];
    #pragma unroll
    for (int i = 0; i < 2; i++)
        #pragma unroll
        for (int j = 0; j < 8; j++)
            #pragma unroll
            for (int t = 0; t < 4; t++) acc[i][j][t] = 0.f;

    for (int k0 = 0; k0 < UNITS; k0 += 32) {
        #pragma unroll
        for (int it = 0; it < 4; it++) {
            int q  = tid + it * 256;
            int m  = q >> 3;
            int k4 = (q & 7) * 4;
            float4 v = *(const float4*)&g_y[(size_t)m * UNITS + k0 + k4];
            uint4 u;
            u.x = f2tf32(v.x); u.y = f2tf32(v.y);
            u.z = f2tf32(v.z); u.w = f2tf32(v.w);
            *(uint4*)&As[m][k4] = u;
        }
        #pragma unroll
        for (int it = 0; it < 4; it++) {
            int q  = tid + it * 256;
            int kk = q >> 5;
            int n4 = (q & 31) * 4;
            float4 v = *(const float4*)&oW[(size_t)(k0 + kk) * VOCAB + colBase + n4];
            uint4 u;
            u.x = f2tf32(v.x); u.y = f2tf32(v.y);
            u.z = f2tf32(v.z); u.w = f2tf32(v.w);
            *(uint4*)&Bs[kk][n4] = u;
        }
        __syncthreads();

        #pragma unroll
        for (int kk = 0; kk < 4; kk++) {
            int kc = kk * 8 + c;
            unsigned a[2][4];
            #pragma unroll
            for (int i = 0; i < 2; i++) {
                int r = mb + i * 16 + g;
                a[i][0] = As[r][kc];
                a[i][1] = As[r + 8][kc];
                a[i][2] = As[r][kc + 4];
                a[i][3] = As[r + 8][kc + 4];
            }
            #pragma unroll
            for (int j = 0; j < 8; j++) {
                int n = nb + j * 8 + g;
                unsigned bb0 = Bs[kc][n];
                unsigned bb1 = Bs[kc + 4][n];
                #pragma unroll
                for (int i = 0; i < 2; i++)
                    mma_tf32(acc[i][j][0], acc[i][j][1], acc[i][j][2], acc[i][j][3],
                             a[i][0], a[i][1], a[i][2], a[i][3], bb0, bb1);
            }
        }
        __syncthreads();
    }

    // epilogue: + ob, store. rows mb+i*16+g (+8); cols colBase+nb+j*8+2c (+1)
    #pragma unroll
    for (int i = 0; i < 2; i++) {
        int m0 = mb + i * 16 + g;
        #pragma unroll
        for (int j = 0; j < 8; j++) {
            int nl = nb + j * 8 + 2 * c;
            int n  = colBase + nl;
            float o0 = obs[nl], o1 = obs[nl + 1];
            float2 lo = make_float2(acc[i][j][0] + o0, acc[i][j][1] + o1);
            float2 hi = make_float2(acc[i][j][2] + o0, acc[i][j][3] + o1);
            *(float2*)&out[(size_t)m0 * VOCAB + n]       = lo;
            *(float2*)&out[(size_t)(m0 + 8) * VOCAB + n] = hi;
        }
    }
}

// =====================================================================
extern "C" void kernel_launch(void* const* d_in, const int* in_sizes, int n_in,
                              void* d_out, int out_size)
{
    const int*   inputs = (const int*)  d_in[0];
    const float* A      = (const float*)d_in[1];   // attention_inputs
    const float* W0     = (const float*)d_in[2];
    const float* b0     = (const float*)d_in[3];
    // d_in[4] = W1   (multiplied by structural zero hidden0 -> unused)
    const float* b1     = (const float*)d_in[5];
    const float* vW     = (const float*)d_in[6];
    // d_in[7] = vb   (uniform shift before softmax -> cancels exactly)
    const float* emb    = (const float*)d_in[8];
    const float* gru_k  = (const float*)d_in[9];
    // d_in[10] = gru_rk (multiplied by structural zero h -> unused)
    const float* gru_b  = (const float*)d_in[11];
    const float* dW     = (const float*)d_in[12];
    const float* db     = (const float*)d_in[13];
    const float* oW     = (const float*)d_in[14];
    const float* ob     = (const float*)d_in[15];

    float* out    = (float*)d_out;
    float* logits = out;                                   // 128*32000
    float* state  = out + (size_t)BATCH * VOCAB;           // 128*512
    float* alpha  = state + (size_t)BATCH * UNITS;         // 128*64

    attn_gemm_kernel<<<dim3(4, 64), 256>>>(A, W0, b0, b1, vW);
    softmax_ctx_kernel<<<BATCH, 256>>>(A, alpha);
    gru_kernel<<<dim3(8, 4), 256>>>(inputs, emb, gru_k, gru_b, state);
    dense_kernel<<<dim3(8, 4), 256>>>(state, dW, db);
    logits_kernel<<<dim3(VOCAB / 128, 1), 256>>>(oW, ob, logits);
}